// round 1
// baseline (speedup 1.0000x reference)
#include <cuda_runtime.h>
#include <math.h>

// Problem constants
namespace {
constexpr int L_  = 16384;
constexpr int C_  = 256;
constexpr int B_  = 4;
constexpr int M_  = B_ * L_;   // 65536 rows
}

// Scratch (allocation-free: __device__ globals)
__device__ float g_Q [(size_t)M_ * C_];      // [B,H,nW,W,d] flat
__device__ float g_Kk[(size_t)M_ * C_];
__device__ float g_V [(size_t)M_ * C_];
__device__ float g_O [(size_t)M_ * C_];      // attention out, [B,H,nW,W,d] flat == [B,L,C] for proj
__device__ float g_X2[(size_t)M_ * C_];      // proj out, reverse-shifted (residual input)
__device__ float g_LN[(size_t)M_ * C_];
__device__ float g_Hh[(size_t)M_ * 4 * C_];  // MLP hidden

// ---------------------------------------------------------------------------
// Generic 128x128 tiled SGEMM, BK=16, 256 threads, 8x8 micro-tile, prefetch.
// MODE 0: A = x with +32 row shift, B = w_qkv [256,768], scatter to Q/K/V
// MODE 1: A = g_O,  B = w_proj [256,256], +bias, write g_X2 at shifted row
// MODE 2: A = g_LN, B = w_mlp1 [256,1024], +bias, exact GELU, write g_Hh
// MODE 3: A = g_Hh, B = w_mlp2 [1024,256], +bias + g_X2 residual, write Out
// ---------------------------------------------------------------------------
template <int MODE>
__global__ void __launch_bounds__(256, 2)
gemm_k(const float* __restrict__ Aext, const float* __restrict__ Bw,
       const float* __restrict__ bias, float* __restrict__ Out)
{
    constexpr int BK = 16;
    constexpr int KK = (MODE == 3) ? 1024 : 256;
    constexpr int NF = (MODE == 0) ? 768 : ((MODE == 2) ? 1024 : 256);

    __shared__ float As[BK][128];
    __shared__ float Bs[BK][128];

    const float* __restrict__ A =
        (MODE == 0) ? Aext : ((MODE == 1) ? g_O : ((MODE == 2) ? g_LN : g_Hh));

    const int tid = threadIdx.x;
    const int m0 = blockIdx.x * 128;
    const int n0 = blockIdx.y * 128;

    // A-tile loader mapping: thread loads rows (alr, alr+64), 4 K-cols at akc
    const int alr = tid >> 2;
    const int akc = (tid & 3) << 2;
    int arow0, arow1;
    {
        int m = m0 + alr;
        if (MODE == 0) { int b = m >> 14, l = m & (L_ - 1); arow0 = (b << 14) | ((l + 32) & (L_ - 1)); }
        else arow0 = m;
        m += 64;
        if (MODE == 0) { int b = m >> 14, l = m & (L_ - 1); arow1 = (b << 14) | ((l + 32) & (L_ - 1)); }
        else arow1 = m;
    }
    const float* Ap0 = A + (size_t)arow0 * KK + akc;
    const float* Ap1 = A + (size_t)arow1 * KK + akc;

    // B-tile loader mapping: thread loads K-rows (bkr, bkr+8), 4 N-cols at bnc
    const int bkr = tid >> 5;
    const int bnc = (tid & 31) << 2;
    const float* Bp0 = Bw + (size_t)bkr * NF + n0 + bnc;
    const float* Bp1 = Bw + (size_t)(bkr + 8) * NF + n0 + bnc;

    float acc[8][8];
#pragma unroll
    for (int i = 0; i < 8; i++)
#pragma unroll
        for (int j = 0; j < 8; j++) acc[i][j] = 0.f;

    // prefetch first tile
    float4 a0 = *(const float4*)(Ap0);
    float4 a1 = *(const float4*)(Ap1);
    float4 b0 = *(const float4*)(Bp0);
    float4 b1 = *(const float4*)(Bp1);

    const int tmo = (tid >> 4) << 3;   // row offset of 8x8 micro-tile
    const int tno = (tid & 15) << 3;   // col offset

    for (int k0 = 0; k0 < KK; k0 += BK) {
        As[akc + 0][alr] = a0.x; As[akc + 1][alr] = a0.y;
        As[akc + 2][alr] = a0.z; As[akc + 3][alr] = a0.w;
        As[akc + 0][alr + 64] = a1.x; As[akc + 1][alr + 64] = a1.y;
        As[akc + 2][alr + 64] = a1.z; As[akc + 3][alr + 64] = a1.w;
        *(float4*)&Bs[bkr][bnc]     = b0;
        *(float4*)&Bs[bkr + 8][bnc] = b1;
        __syncthreads();

        const int kn = k0 + BK;
        if (kn < KK) {
            a0 = *(const float4*)(Ap0 + kn);
            a1 = *(const float4*)(Ap1 + kn);
            b0 = *(const float4*)(Bp0 + (size_t)kn * NF);
            b1 = *(const float4*)(Bp1 + (size_t)kn * NF);
        }

#pragma unroll
        for (int k = 0; k < BK; k++) {
            float ra[8], rb[8];
            *(float4*)(ra)     = *(const float4*)&As[k][tmo];
            *(float4*)(ra + 4) = *(const float4*)&As[k][tmo + 4];
            *(float4*)(rb)     = *(const float4*)&Bs[k][tno];
            *(float4*)(rb + 4) = *(const float4*)&Bs[k][tno + 4];
#pragma unroll
            for (int i = 0; i < 8; i++)
#pragma unroll
                for (int j = 0; j < 8; j++)
                    acc[i][j] = fmaf(ra[i], rb[j], acc[i][j]);
        }
        __syncthreads();
    }

    // ---- epilogue ----
#pragma unroll
    for (int i = 0; i < 8; i++) {
        const int m  = m0 + tmo + i;
        const int nn = n0 + tno;          // 8 consecutive output cols

        if (MODE == 0) {
            // scatter qkv[m][nn..nn+7] -> {Q,K,V}[b][h][n][w][dd..dd+7]
            const int b = m >> 14, l = m & (L_ - 1);
            const int n = l >> 6, w = l & 63;
            const int s  = nn >> 8;
            const int hd = nn & 255;
            const int h  = hd >> 5, dd = hd & 31;
            float* base = (s == 0 ? g_Q : (s == 1 ? g_Kk : g_V));
            float* dst  = base + ((size_t)((b * 8 + h) * 256 + n)) * 2048 + w * 32 + dd;
            *(float4*)(dst)     = make_float4(acc[i][0], acc[i][1], acc[i][2], acc[i][3]);
            *(float4*)(dst + 4) = make_float4(acc[i][4], acc[i][5], acc[i][6], acc[i][7]);
        } else if (MODE == 1) {
            // +bias, reverse shift: merged row l -> x2 row (l+32) mod L
            const int b = m >> 14, l = m & (L_ - 1);
            const int dr = (b << 14) | ((l + 32) & (L_ - 1));
            float* dst = g_X2 + (size_t)dr * 256 + nn;
            float v[8];
#pragma unroll
            for (int j = 0; j < 8; j++) v[j] = acc[i][j] + bias[nn + j];
            *(float4*)(dst)     = make_float4(v[0], v[1], v[2], v[3]);
            *(float4*)(dst + 4) = make_float4(v[4], v[5], v[6], v[7]);
        } else if (MODE == 2) {
            float* dst = g_Hh + (size_t)m * 1024 + nn;
            float v[8];
#pragma unroll
            for (int j = 0; j < 8; j++) {
                float t = acc[i][j] + bias[nn + j];
                v[j] = 0.5f * t * (1.0f + erff(t * 0.70710678118654752f));
            }
            *(float4*)(dst)     = make_float4(v[0], v[1], v[2], v[3]);
            *(float4*)(dst + 4) = make_float4(v[4], v[5], v[6], v[7]);
        } else {
            const float* r2 = g_X2 + (size_t)m * 256 + nn;
            float4 x0 = *(const float4*)r2;
            float4 x1 = *(const float4*)(r2 + 4);
            float* dst = Out + (size_t)m * 256 + nn;
            *(float4*)(dst) = make_float4(acc[i][0] + bias[nn + 0] + x0.x,
                                          acc[i][1] + bias[nn + 1] + x0.y,
                                          acc[i][2] + bias[nn + 2] + x0.z,
                                          acc[i][3] + bias[nn + 3] + x0.w);
            *(float4*)(dst + 4) = make_float4(acc[i][4] + bias[nn + 4] + x1.x,
                                              acc[i][5] + bias[nn + 5] + x1.y,
                                              acc[i][6] + bias[nn + 6] + x1.z,
                                              acc[i][7] + bias[nn + 7] + x1.w);
        }
    }
}

// ---------------------------------------------------------------------------
// Windowed attention: one block per (b,h,window). 64x32 q,k,v tiles in smem.
// ---------------------------------------------------------------------------
__global__ void __launch_bounds__(256)
attn_k()
{
    const int wh = blockIdx.x;                 // ((b*8+h)*256+n)
    const float* __restrict__ qb = g_Q  + (size_t)wh * 2048;
    const float* __restrict__ kb = g_Kk + (size_t)wh * 2048;
    const float* __restrict__ vb = g_V  + (size_t)wh * 2048;

    __shared__ float sq[64][33];
    __shared__ float sk[64][33];
    __shared__ float sv[64][33];
    __shared__ float sp[64][65];

    const int tid = threadIdx.x;
    for (int i = tid; i < 2048; i += 256) {
        const int r = i >> 5, c = i & 31;
        sq[r][c] = qb[i];
        sk[r][c] = kb[i];
        sv[r][c] = vb[i];
    }
    __syncthreads();

    const int r = tid >> 2;        // 0..63 : q row
    const int cseg = tid & 3;      // 4 threads per row

    float qr[32];
#pragma unroll
    for (int d2 = 0; d2 < 32; d2++) qr[d2] = sq[r][d2];

    // S row segment (16 cols)
    float sc[16];
#pragma unroll
    for (int cc = 0; cc < 16; cc++) {
        const int c = cseg * 16 + cc;
        float a = 0.f;
#pragma unroll
        for (int d2 = 0; d2 < 32; d2++) a = fmaf(qr[d2], sk[c][d2], a);
        sc[cc] = a * 0.1767766952966369f;   // 1/sqrt(32)
    }

    // softmax over 64 (4 threads cooperate, consecutive lanes)
    float mx = sc[0];
#pragma unroll
    for (int cc = 1; cc < 16; cc++) mx = fmaxf(mx, sc[cc]);
    mx = fmaxf(mx, __shfl_xor_sync(0xffffffffu, mx, 1));
    mx = fmaxf(mx, __shfl_xor_sync(0xffffffffu, mx, 2));
    float sum = 0.f;
#pragma unroll
    for (int cc = 0; cc < 16; cc++) { sc[cc] = __expf(sc[cc] - mx); sum += sc[cc]; }
    sum += __shfl_xor_sync(0xffffffffu, sum, 1);
    sum += __shfl_xor_sync(0xffffffffu, sum, 2);
    const float inv = 1.f / sum;
#pragma unroll
    for (int cc = 0; cc < 16; cc++) sp[r][cseg * 16 + cc] = sc[cc] * inv;
    __syncthreads();

    // O = P @ V ; thread computes 8 of 32 d-cols for its row
    float o[8] = {0, 0, 0, 0, 0, 0, 0, 0};
    const int c0 = cseg * 8;
#pragma unroll
    for (int j = 0; j < 64; j++) {
        const float p = sp[r][j];
#pragma unroll
        for (int c = 0; c < 8; c++) o[c] = fmaf(p, sv[j][c0 + c], o[c]);
    }
    float* ob = g_O + (size_t)wh * 2048 + r * 32 + c0;
    *(float4*)(ob)     = make_float4(o[0], o[1], o[2], o[3]);
    *(float4*)(ob + 4) = make_float4(o[4], o[5], o[6], o[7]);
}

// ---------------------------------------------------------------------------
// LayerNorm over C=256: 8 rows / block, 32 threads / row.
// ---------------------------------------------------------------------------
__global__ void __launch_bounds__(256)
ln_k(const float* __restrict__ gamma, const float* __restrict__ beta)
{
    const int row  = blockIdx.x * 8 + (threadIdx.x >> 5);
    const int lane = threadIdx.x & 31;
    const float* xr = g_X2 + (size_t)row * 256 + lane * 8;
    float4 v0 = *(const float4*)xr;
    float4 v1 = *(const float4*)(xr + 4);

    float s = v0.x + v0.y + v0.z + v0.w + v1.x + v1.y + v1.z + v1.w;
#pragma unroll
    for (int o = 16; o > 0; o >>= 1) s += __shfl_xor_sync(0xffffffffu, s, o);
    const float mu = s * (1.f / 256.f);

    float vv[8] = {v0.x - mu, v0.y - mu, v0.z - mu, v0.w - mu,
                   v1.x - mu, v1.y - mu, v1.z - mu, v1.w - mu};
    float q = 0.f;
#pragma unroll
    for (int i = 0; i < 8; i++) q += vv[i] * vv[i];
#pragma unroll
    for (int o = 16; o > 0; o >>= 1) q += __shfl_xor_sync(0xffffffffu, q, o);
    const float inv = rsqrtf(q * (1.f / 256.f) + 1e-5f);

    const float* g  = gamma + lane * 8;
    const float* bb = beta  + lane * 8;
    float* dst = g_LN + (size_t)row * 256 + lane * 8;
    *(float4*)(dst) = make_float4(vv[0] * inv * g[0] + bb[0],
                                  vv[1] * inv * g[1] + bb[1],
                                  vv[2] * inv * g[2] + bb[2],
                                  vv[3] * inv * g[3] + bb[3]);
    *(float4*)(dst + 4) = make_float4(vv[4] * inv * g[4] + bb[4],
                                      vv[5] * inv * g[5] + bb[5],
                                      vv[6] * inv * g[6] + bb[6],
                                      vv[7] * inv * g[7] + bb[7]);
}

// ---------------------------------------------------------------------------
extern "C" void kernel_launch(void* const* d_in, const int* in_sizes, int n_in,
                              void* d_out, int out_size)
{
    const float* x      = (const float*)d_in[0];
    const float* w_qkv  = (const float*)d_in[1];
    const float* w_proj = (const float*)d_in[2];
    const float* b_proj = (const float*)d_in[3];
    const float* gamma2 = (const float*)d_in[4];
    const float* beta2  = (const float*)d_in[5];
    const float* w_mlp1 = (const float*)d_in[6];
    const float* b_mlp1 = (const float*)d_in[7];
    const float* w_mlp2 = (const float*)d_in[8];
    const float* b_mlp2 = (const float*)d_in[9];
    float* out = (float*)d_out;

    gemm_k<0><<<dim3(512, 6), 256>>>(x, w_qkv, nullptr, nullptr);       // QKV (+shift)
    attn_k<<<8192, 256>>>();                                            // windowed attention
    gemm_k<1><<<dim3(512, 2), 256>>>(nullptr, w_proj, b_proj, nullptr); // proj (+unshift)
    ln_k<<<8192, 256>>>(gamma2, beta2);                                 // LayerNorm
    gemm_k<2><<<dim3(512, 8), 256>>>(nullptr, w_mlp1, b_mlp1, nullptr); // MLP1 + GELU
    gemm_k<3><<<dim3(512, 2), 256>>>(nullptr, w_mlp2, b_mlp2, out);     // MLP2 + residual
}

// round 3
// speedup vs baseline: 2.0374x; 2.0374x over previous
#include <cuda_runtime.h>
#include <math.h>
#include <stdint.h>

namespace {
constexpr int L_ = 16384;
constexpr int C_ = 256;
constexpr int B_ = 4;
constexpr int M_ = B_ * L_;   // 65536
}

// Scratch (allocation-free: __device__ globals)
__device__ float g_Q [(size_t)M_ * C_];      // [B,H,nW,W,d] flat
__device__ float g_Kk[(size_t)M_ * C_];
__device__ float g_V [(size_t)M_ * C_];
__device__ float g_O [(size_t)M_ * C_];      // attention out, flat == proj input
__device__ float g_X2[(size_t)M_ * C_];      // proj out (reverse-shifted) = residual
__device__ float g_LN[(size_t)M_ * C_];
__device__ float g_Hh[(size_t)M_ * 4 * C_];  // MLP hidden

__device__ __forceinline__ uint32_t f2tf(float x) {
    uint32_t r;
    asm("cvt.rna.tf32.f32 %0, %1;" : "=r"(r) : "f"(x));
    return r;
}

__device__ __forceinline__ void mma8(float& c0, float& c1, float& c2, float& c3,
                                     uint32_t a0, uint32_t a1, uint32_t a2, uint32_t a3,
                                     uint32_t b0, uint32_t b1) {
    asm volatile("mma.sync.aligned.m16n8k8.row.col.f32.tf32.tf32.f32 "
                 "{%0,%1,%2,%3}, {%4,%5,%6,%7}, {%8,%9}, {%0,%1,%2,%3};"
                 : "+f"(c0), "+f"(c1), "+f"(c2), "+f"(c3)
                 : "r"(a0), "r"(a1), "r"(a2), "r"(a3), "r"(b0), "r"(b1));
}

// Epilogue store of 2 consecutive output cols (n even).
template <int MODE>
__device__ __forceinline__ void store2(int m, int n, float v0, float v1,
                                       const float* __restrict__ bias,
                                       float* __restrict__ Out)
{
    if (MODE == 0) {
        // scatter qkv[m][n,n+1] -> {Q,K,V}[b][h][win][w][dd,dd+1]
        const int b = m >> 14, l = m & (L_ - 1);
        const int win = l >> 6, w = l & 63;
        const int s = n >> 8, hd = n & 255, h = hd >> 5, dd = hd & 31;
        float* base = (s == 0 ? g_Q : (s == 1 ? g_Kk : g_V));
        float* dst = base + ((size_t)((b * 8 + h) * 256 + win)) * 2048 + w * 32 + dd;
        *(float2*)dst = make_float2(v0, v1);
    } else if (MODE == 1) {
        // +bias, reverse shift: merged row l -> x2 row (l+32) mod L
        const int b = m >> 14, l = m & (L_ - 1);
        const int dr = (b << 14) | ((l + 32) & (L_ - 1));
        const float2 bv = *(const float2*)(bias + n);
        *(float2*)(g_X2 + (size_t)dr * 256 + n) = make_float2(v0 + bv.x, v1 + bv.y);
    } else if (MODE == 2) {
        const float2 bv = *(const float2*)(bias + n);
        float t0 = v0 + bv.x, t1 = v1 + bv.y;
        t0 = 0.5f * t0 * (1.0f + erff(t0 * 0.7071067811865475f));
        t1 = 0.5f * t1 * (1.0f + erff(t1 * 0.7071067811865475f));
        *(float2*)(g_Hh + (size_t)m * 1024 + n) = make_float2(t0, t1);
    } else {
        const float2 bv = *(const float2*)(bias + n);
        const float2 x = *(const float2*)(g_X2 + (size_t)m * 256 + n);
        *(float2*)(Out + (size_t)m * 256 + n) =
            make_float2(v0 + bv.x + x.x, v1 + bv.y + x.y);
    }
}

// ---------------------------------------------------------------------------
// TF32 tensor-core GEMM: 128x128 tile, BK=32, 256 threads (8 warps 2x4),
// warp tile 64x32 via m16n8k8. fp32->tf32 conversion in the STS path.
// MODE 0: A = x (+32 shift), B = w_qkv [256,768], scatter Q/K/V
// MODE 1: A = g_O,  B = w_proj [256,256],  +bias, unshift -> g_X2
// MODE 2: A = g_LN, B = w_mlp1 [256,1024], +bias, exact GELU -> g_Hh
// MODE 3: A = g_Hh, B = w_mlp2 [1024,256], +bias + residual -> Out
// ---------------------------------------------------------------------------
template <int MODE>
__global__ void __launch_bounds__(256)
gemm_tc(const float* __restrict__ Aext, const float* __restrict__ Bw,
        const float* __restrict__ bias, float* __restrict__ Out)
{
    constexpr int KK = (MODE == 3) ? 1024 : 256;
    constexpr int NF = (MODE == 0) ? 768 : ((MODE == 2) ? 1024 : 256);

    __shared__ uint32_t As[128][36];   // m-major, pad -> conflict-free frag loads
    __shared__ uint32_t Bs[32][132];   // k-major

    const float* __restrict__ A =
        (MODE == 0) ? Aext : ((MODE == 1) ? g_O : ((MODE == 2) ? g_LN : g_Hh));

    const int tid = threadIdx.x;
    const int m0 = blockIdx.x * 128;
    const int n0 = blockIdx.y * 128;

    // A loader: pass p loads local row p*32 + tid/8, k-cols (tid%8)*4 .. +3
    const int alr = tid >> 3;          // 0..31
    const int akc = (tid & 7) << 2;    // 0,4,..,28
    const float* Ap[4];
#pragma unroll
    for (int p = 0; p < 4; p++) {
        int m = m0 + p * 32 + alr;
        int row;
        if (MODE == 0) { int b = m >> 14, l = m & (L_ - 1); row = (b << 14) | ((l + 32) & (L_ - 1)); }
        else row = m;
        Ap[p] = A + (size_t)row * KK + akc;
    }

    // B loader: pass p loads k-row p*8 + tid/32, n-cols (tid%32)*4 .. +3
    const int bkr = tid >> 5;          // 0..7
    const int bnc = (tid & 31) << 2;   // 0..124
    const float* Bp = Bw + (size_t)bkr * NF + n0 + bnc;

    float acc[4][4][4];
#pragma unroll
    for (int i = 0; i < 4; i++)
#pragma unroll
        for (int j = 0; j < 4; j++)
#pragma unroll
            for (int q = 0; q < 4; q++) acc[i][j][q] = 0.f;

    float4 aPre[4], bPre[4];
#pragma unroll
    for (int p = 0; p < 4; p++) aPre[p] = *(const float4*)(Ap[p]);
#pragma unroll
    for (int p = 0; p < 4; p++) bPre[p] = *(const float4*)(Bp + (size_t)(p * 8) * NF);

    const int wid = tid >> 5, lane = tid & 31;
    const int wm = (wid >> 2) * 64;    // warp row offset
    const int wn = (wid & 3) * 32;     // warp col offset
    const int lr = lane >> 2, lc = lane & 3;

    for (int k0 = 0; k0 < KK; k0 += 32) {
        // STS with tf32 conversion
#pragma unroll
        for (int p = 0; p < 4; p++) {
            uint32_t* d = &As[p * 32 + alr][akc];
            d[0] = f2tf(aPre[p].x); d[1] = f2tf(aPre[p].y);
            d[2] = f2tf(aPre[p].z); d[3] = f2tf(aPre[p].w);
        }
#pragma unroll
        for (int p = 0; p < 4; p++) {
            uint32_t* d = &Bs[p * 8 + bkr][bnc];
            d[0] = f2tf(bPre[p].x); d[1] = f2tf(bPre[p].y);
            d[2] = f2tf(bPre[p].z); d[3] = f2tf(bPre[p].w);
        }
        __syncthreads();

        const int kn = k0 + 32;
        if (kn < KK) {
#pragma unroll
            for (int p = 0; p < 4; p++) aPre[p] = *(const float4*)(Ap[p] + kn);
#pragma unroll
            for (int p = 0; p < 4; p++) bPre[p] = *(const float4*)(Bp + (size_t)(kn + p * 8) * NF);
        }

#pragma unroll
        for (int ks = 0; ks < 32; ks += 8) {
            uint32_t af[4][4], bf[4][2];
#pragma unroll
            for (int i = 0; i < 4; i++) {
                const int rm = wm + i * 16 + lr;
                af[i][0] = As[rm][ks + lc];
                af[i][1] = As[rm + 8][ks + lc];
                af[i][2] = As[rm][ks + lc + 4];
                af[i][3] = As[rm + 8][ks + lc + 4];
            }
#pragma unroll
            for (int j = 0; j < 4; j++) {
                const int cn = wn + j * 8 + lr;
                bf[j][0] = Bs[ks + lc][cn];
                bf[j][1] = Bs[ks + lc + 4][cn];
            }
#pragma unroll
            for (int i = 0; i < 4; i++)
#pragma unroll
                for (int j = 0; j < 4; j++)
                    mma8(acc[i][j][0], acc[i][j][1], acc[i][j][2], acc[i][j][3],
                         af[i][0], af[i][1], af[i][2], af[i][3],
                         bf[j][0], bf[j][1]);
        }
        __syncthreads();
    }

    // epilogue: each (i,j) owns rows (lo, lo+8), cols n..n+1
#pragma unroll
    for (int i = 0; i < 4; i++) {
#pragma unroll
        for (int j = 0; j < 4; j++) {
            const int mlo = m0 + wm + i * 16 + lr;
            const int nn  = n0 + wn + j * 8 + 2 * lc;
            store2<MODE>(mlo,     nn, acc[i][j][0], acc[i][j][1], bias, Out);
            store2<MODE>(mlo + 8, nn, acc[i][j][2], acc[i][j][3], bias, Out);
        }
    }
}

// ---------------------------------------------------------------------------
// Windowed attention: one block per (b,h,window). 64x32 q,k,v tiles in smem.
// ---------------------------------------------------------------------------
__global__ void __launch_bounds__(256)
attn_k()
{
    const int wh = blockIdx.x;                 // ((b*8+h)*256+n)
    const float* __restrict__ qb = g_Q  + (size_t)wh * 2048;
    const float* __restrict__ kb = g_Kk + (size_t)wh * 2048;
    const float* __restrict__ vb = g_V  + (size_t)wh * 2048;

    __shared__ float sq[64][33];
    __shared__ float sk[64][33];
    __shared__ float sv[64][33];
    __shared__ float sp[64][65];

    const int tid = threadIdx.x;
    for (int i = tid; i < 2048; i += 256) {
        const int r = i >> 5, c = i & 31;
        sq[r][c] = qb[i];
        sk[r][c] = kb[i];
        sv[r][c] = vb[i];
    }
    __syncthreads();

    const int r = tid >> 2;        // 0..63 : q row
    const int cseg = tid & 3;      // 4 threads per row

    float qr[32];
#pragma unroll
    for (int d2 = 0; d2 < 32; d2++) qr[d2] = sq[r][d2];

    float sc[16];
#pragma unroll
    for (int cc = 0; cc < 16; cc++) {
        const int c = cseg * 16 + cc;
        float a = 0.f;
#pragma unroll
        for (int d2 = 0; d2 < 32; d2++) a = fmaf(qr[d2], sk[c][d2], a);
        sc[cc] = a * 0.1767766952966369f;   // 1/sqrt(32)
    }

    float mx = sc[0];
#pragma unroll
    for (int cc = 1; cc < 16; cc++) mx = fmaxf(mx, sc[cc]);
    mx = fmaxf(mx, __shfl_xor_sync(0xffffffffu, mx, 1));
    mx = fmaxf(mx, __shfl_xor_sync(0xffffffffu, mx, 2));
    float sum = 0.f;
#pragma unroll
    for (int cc = 0; cc < 16; cc++) { sc[cc] = __expf(sc[cc] - mx); sum += sc[cc]; }
    sum += __shfl_xor_sync(0xffffffffu, sum, 1);
    sum += __shfl_xor_sync(0xffffffffu, sum, 2);
    const float inv = 1.f / sum;
#pragma unroll
    for (int cc = 0; cc < 16; cc++) sp[r][cseg * 16 + cc] = sc[cc] * inv;
    __syncthreads();

    float o[8] = {0, 0, 0, 0, 0, 0, 0, 0};
    const int c0 = cseg * 8;
#pragma unroll
    for (int j = 0; j < 64; j++) {
        const float p = sp[r][j];
#pragma unroll
        for (int c = 0; c < 8; c++) o[c] = fmaf(p, sv[j][c0 + c], o[c]);
    }
    float* ob = g_O + (size_t)wh * 2048 + r * 32 + c0;
    *(float4*)(ob)     = make_float4(o[0], o[1], o[2], o[3]);
    *(float4*)(ob + 4) = make_float4(o[4], o[5], o[6], o[7]);
}

// ---------------------------------------------------------------------------
// LayerNorm over C=256: 8 rows / block, 32 threads / row.
// ---------------------------------------------------------------------------
__global__ void __launch_bounds__(256)
ln_k(const float* __restrict__ gamma, const float* __restrict__ beta)
{
    const int row  = blockIdx.x * 8 + (threadIdx.x >> 5);
    const int lane = threadIdx.x & 31;
    const float* xr = g_X2 + (size_t)row * 256 + lane * 8;
    float4 v0 = *(const float4*)xr;
    float4 v1 = *(const float4*)(xr + 4);

    float s = v0.x + v0.y + v0.z + v0.w + v1.x + v1.y + v1.z + v1.w;
#pragma unroll
    for (int o = 16; o > 0; o >>= 1) s += __shfl_xor_sync(0xffffffffu, s, o);
    const float mu = s * (1.f / 256.f);

    float vv[8] = {v0.x - mu, v0.y - mu, v0.z - mu, v0.w - mu,
                   v1.x - mu, v1.y - mu, v1.z - mu, v1.w - mu};
    float q = 0.f;
#pragma unroll
    for (int i = 0; i < 8; i++) q += vv[i] * vv[i];
#pragma unroll
    for (int o = 16; o > 0; o >>= 1) q += __shfl_xor_sync(0xffffffffu, q, o);
    const float inv = rsqrtf(q * (1.f / 256.f) + 1e-5f);

    const float* g  = gamma + lane * 8;
    const float* bb = beta  + lane * 8;
    float* dst = g_LN + (size_t)row * 256 + lane * 8;
    *(float4*)(dst) = make_float4(vv[0] * inv * g[0] + bb[0],
                                  vv[1] * inv * g[1] + bb[1],
                                  vv[2] * inv * g[2] + bb[2],
                                  vv[3] * inv * g[3] + bb[3]);
    *(float4*)(dst + 4) = make_float4(vv[4] * inv * g[4] + bb[4],
                                      vv[5] * inv * g[5] + bb[5],
                                      vv[6] * inv * g[6] + bb[6],
                                      vv[7] * inv * g[7] + bb[7]);
}

// ---------------------------------------------------------------------------
extern "C" void kernel_launch(void* const* d_in, const int* in_sizes, int n_in,
                              void* d_out, int out_size)
{
    const float* x      = (const float*)d_in[0];
    const float* w_qkv  = (const float*)d_in[1];
    const float* w_proj = (const float*)d_in[2];
    const float* b_proj = (const float*)d_in[3];
    const float* gamma2 = (const float*)d_in[4];
    const float* beta2  = (const float*)d_in[5];
    const float* w_mlp1 = (const float*)d_in[6];
    const float* b_mlp1 = (const float*)d_in[7];
    const float* w_mlp2 = (const float*)d_in[8];
    const float* b_mlp2 = (const float*)d_in[9];
    float* out = (float*)d_out;

    gemm_tc<0><<<dim3(512, 6), 256>>>(x, w_qkv, nullptr, nullptr);       // QKV (+shift)
    attn_k<<<8192, 256>>>();                                             // windowed attention
    gemm_tc<1><<<dim3(512, 2), 256>>>(nullptr, w_proj, b_proj, nullptr); // proj (+unshift)
    ln_k<<<8192, 256>>>(gamma2, beta2);                                  // LayerNorm
    gemm_tc<2><<<dim3(512, 8), 256>>>(nullptr, w_mlp1, b_mlp1, nullptr); // MLP1 + GELU
    gemm_tc<3><<<dim3(512, 2), 256>>>(nullptr, w_mlp2, b_mlp2, out);     // MLP2 + residual
}